// round 7
// baseline (speedup 1.0000x reference)
#include <cuda_runtime.h>
#include <cstdint>

// ---------------------------------------------------------------------------
// AnomalyAttention B=16, N=1024, C=256 — mma.sync tf32, 128x256 CTA tiles,
// P overlapped on a forked stream.
// Outputs: Z [B,N,C] | P [B,N,N] | S [B,N,N]
// ---------------------------------------------------------------------------

#define BB 16
#define NN 1024
#define CC 256

static const long long OFF_Z = 0;
static const long long OFF_P = (long long)BB * NN * CC;
static const long long OFF_S = OFF_P + (long long)BB * NN * NN;

__device__ float g_QKV[(size_t)3 * BB * NN * CC];     // Q|K|V (tf32-rounded)
__device__ float g_scores[(size_t)BB * NN * NN];      // raw scores

// ---------------------------------------------------------------------------
__device__ __forceinline__ uint32_t smem_u32(const void* p) {
    uint32_t a;
    asm("{ .reg .u64 t; cvta.to.shared.u64 t, %1; cvt.u32.u64 %0, t; }"
        : "=r"(a) : "l"(p));
    return a;
}
__device__ __forceinline__ float tf32r(float x) {
    float y; asm("cvt.rna.tf32.f32 %0, %1;" : "=f"(y) : "f"(x)); return y;
}
__device__ __forceinline__ uint32_t tf32u(uint32_t x) {
    float y = tf32r(__uint_as_float(x)); return __float_as_uint(y);
}

// ---------------------------------------------------------------------------
// mma.sync tf32 GEMM, CTA tile 128x256, 256 threads = 8 warps (2M x 4N),
// warp tile 64x64, BK=32, 3-stage cp.async ring.
//   BNMAJ=false: C = alpha * A * B^T   (B [N,K] K-major, ldb=K)
//   BNMAJ=true : C = alpha * A * B     (B [K,N] N-major, ldb)
//   MULTIB: B selected from {B0,B1,B2} by blockIdx.z (shared A).
//   RA/RB: round fragments to tf32 (rna) in-register. RO: round outputs.
// Bank-conflict-free: A/B K-major pad 36 (bank (4g+t)%32 bijective);
// B N-major pad 264 (bank (8t+g)%32 bijective).
// ---------------------------------------------------------------------------
template <bool BNMAJ, bool MULTIB, bool RA, bool RB, bool RO>
__global__ __launch_bounds__(256, 1) void mma_gemm(
    const float* __restrict__ A, const float* __restrict__ B0,
    const float* __restrict__ B1, const float* __restrict__ B2,
    float* __restrict__ C,
    int K, int ldb, int ldc, float alpha,
    long long sA, long long sB, long long sC)
{
    constexpr int BM = 128, BN = 256, BK = 32, PAD = 36, PADN = 264;
    constexpr int ASTG = BM * PAD;                        // 4608 floats
    constexpr int BSTG = BNMAJ ? BK * PADN : BN * PAD;    // 8448 / 9216
    extern __shared__ float sm[];
    float* As = sm;                  // [3][ASTG]
    float* Bs = sm + 3 * ASTG;       // [3][BSTG]

    const int z = blockIdx.z;
    const float* B = MULTIB ? (z == 0 ? B0 : (z == 1 ? B1 : B2))
                            : B0 + (long long)z * sB;
    A += (long long)z * sA;
    C += (long long)z * sC;

    const int tid = threadIdx.x, lane = tid & 31, wid = tid >> 5;
    const int wm = wid >> 2, wn = wid & 3;               // 2 x 4 warp grid
    const int g = lane >> 2, t = lane & 3;
    const long long arow0 = (long long)blockIdx.y * BM;
    const long long bcol0 = (long long)blockIdx.x * BN;

    const int nch = K / BK;

    auto issue = [&](int j) {
        if (j < nch) {
            const int st = j % 3;
            float* as = As + st * ASTG;
            float* bs = Bs + st * BSTG;
            #pragma unroll
            for (int i = 0; i < 4; i++) {               // A: 1024 chunks of 16B
                const int ch = tid + 256 * i;
                const int row = ch >> 3, c16 = ch & 7;
                const uint32_t da = smem_u32(&as[row * PAD + c16 * 4]);
                const float* pa = A + (arow0 + row) * K + (long long)j * BK + c16 * 4;
                asm volatile("cp.async.cg.shared.global [%0], [%1], 16;"
                             :: "r"(da), "l"(pa) : "memory");
            }
            #pragma unroll
            for (int i = 0; i < 8; i++) {               // B: 2048 chunks of 16B
                const int ch = tid + 256 * i;
                if (BNMAJ) {   // 32 k-rows x 64 chunks
                    const int row = ch >> 6, c4 = (ch & 63) * 4;
                    const uint32_t db = smem_u32(&bs[row * PADN + c4]);
                    const float* pb = B + ((long long)j * BK + row) * ldb + bcol0 + c4;
                    asm volatile("cp.async.cg.shared.global [%0], [%1], 16;"
                                 :: "r"(db), "l"(pb) : "memory");
                } else {       // 256 n-rows x 8 chunks
                    const int row = ch >> 3, c16 = ch & 7;
                    const uint32_t db = smem_u32(&bs[row * PAD + c16 * 4]);
                    const float* pb = B + (bcol0 + row) * ldb + (long long)j * BK + c16 * 4;
                    asm volatile("cp.async.cg.shared.global [%0], [%1], 16;"
                                 :: "r"(db), "l"(pb) : "memory");
                }
            }
        }
        asm volatile("cp.async.commit_group;" ::: "memory");
    };

    float acc[4][8][4];
    #pragma unroll
    for (int i = 0; i < 4; i++)
        #pragma unroll
        for (int jn = 0; jn < 8; jn++)
            #pragma unroll
            for (int r = 0; r < 4; r++) acc[i][jn][r] = 0.f;

    issue(0);
    issue(1);

    for (int j = 0; j < nch; j++) {
        if (j == nch - 1) asm volatile("cp.async.wait_group 0;" ::: "memory");
        else              asm volatile("cp.async.wait_group 1;" ::: "memory");
        __syncthreads();
        issue(j + 2);

        const float* a_ = As + (j % 3) * ASTG;
        const float* b_ = Bs + (j % 3) * BSTG;

        #pragma unroll
        for (int ks = 0; ks < 4; ks++) {
            uint32_t af[4][4], bf[8][2];
            #pragma unroll
            for (int mt = 0; mt < 4; mt++) {
                const int r = wm * 64 + mt * 16 + g;
                const int c = ks * 8 + t;
                af[mt][0] = __float_as_uint(a_[r * PAD + c]);
                af[mt][1] = __float_as_uint(a_[(r + 8) * PAD + c]);
                af[mt][2] = __float_as_uint(a_[r * PAD + c + 4]);
                af[mt][3] = __float_as_uint(a_[(r + 8) * PAD + c + 4]);
                if (RA) {
                    af[mt][0] = tf32u(af[mt][0]); af[mt][1] = tf32u(af[mt][1]);
                    af[mt][2] = tf32u(af[mt][2]); af[mt][3] = tf32u(af[mt][3]);
                }
            }
            #pragma unroll
            for (int nt = 0; nt < 8; nt++) {
                const int n = wn * 64 + nt * 8 + g;
                if (BNMAJ) {
                    bf[nt][0] = __float_as_uint(b_[(ks * 8 + t) * PADN + n]);
                    bf[nt][1] = __float_as_uint(b_[(ks * 8 + t + 4) * PADN + n]);
                } else {
                    bf[nt][0] = __float_as_uint(b_[n * PAD + ks * 8 + t]);
                    bf[nt][1] = __float_as_uint(b_[n * PAD + ks * 8 + t + 4]);
                }
                if (RB) { bf[nt][0] = tf32u(bf[nt][0]); bf[nt][1] = tf32u(bf[nt][1]); }
            }
            #pragma unroll
            for (int mt = 0; mt < 4; mt++)
                #pragma unroll
                for (int nt = 0; nt < 8; nt++)
                    asm volatile(
                        "mma.sync.aligned.m16n8k8.row.col.f32.tf32.tf32.f32 "
                        "{%0,%1,%2,%3}, {%4,%5,%6,%7}, {%8,%9}, {%0,%1,%2,%3};"
                        : "+f"(acc[mt][nt][0]), "+f"(acc[mt][nt][1]),
                          "+f"(acc[mt][nt][2]), "+f"(acc[mt][nt][3])
                        : "r"(af[mt][0]), "r"(af[mt][1]), "r"(af[mt][2]), "r"(af[mt][3]),
                          "r"(bf[nt][0]), "r"(bf[nt][1]));
        }
    }

    #pragma unroll
    for (int mt = 0; mt < 4; mt++) {
        const long long gr = arow0 + wm * 64 + mt * 16 + g;
        #pragma unroll
        for (int nt = 0; nt < 8; nt++) {
            const long long gc = bcol0 + wn * 64 + nt * 8 + 2 * t;
            float2 v0 = make_float2(acc[mt][nt][0] * alpha, acc[mt][nt][1] * alpha);
            float2 v1 = make_float2(acc[mt][nt][2] * alpha, acc[mt][nt][3] * alpha);
            if (RO) {
                v0.x = tf32r(v0.x); v0.y = tf32r(v0.y);
                v1.x = tf32r(v1.x); v1.y = tf32r(v1.y);
            }
            *reinterpret_cast<float2*>(&C[gr * ldc + gc])       = v0;
            *reinterpret_cast<float2*>(&C[(gr + 8) * ldc + gc]) = v1;
        }
    }
}

// ---------------------------------------------------------------------------
// softmax over batch dim (axis=0), float4-vectorized: exact S -> out
// ---------------------------------------------------------------------------
__global__ __launch_bounds__(256) void batch_softmax_kernel(
    const float* __restrict__ scores, float* __restrict__ S)
{
    size_t idx = ((size_t)blockIdx.x * blockDim.x + threadIdx.x) * 4;
    float4 v[BB];
    float4 mx = make_float4(-1e30f, -1e30f, -1e30f, -1e30f);
    #pragma unroll
    for (int b = 0; b < BB; b++) {
        v[b] = *reinterpret_cast<const float4*>(&scores[(size_t)b * NN * NN + idx]);
        mx.x = fmaxf(mx.x, v[b].x); mx.y = fmaxf(mx.y, v[b].y);
        mx.z = fmaxf(mx.z, v[b].z); mx.w = fmaxf(mx.w, v[b].w);
    }
    float4 s = make_float4(0.f, 0.f, 0.f, 0.f);
    #pragma unroll
    for (int b = 0; b < BB; b++) {
        v[b].x = __expf(v[b].x - mx.x); s.x += v[b].x;
        v[b].y = __expf(v[b].y - mx.y); s.y += v[b].y;
        v[b].z = __expf(v[b].z - mx.z); s.z += v[b].z;
        v[b].w = __expf(v[b].w - mx.w); s.w += v[b].w;
    }
    const float4 inv = make_float4(1.f / s.x, 1.f / s.y, 1.f / s.z, 1.f / s.w);
    #pragma unroll
    for (int b = 0; b < BB; b++) {
        float4 o = make_float4(v[b].x * inv.x, v[b].y * inv.y,
                               v[b].z * inv.z, v[b].w * inv.w);
        *reinterpret_cast<float4*>(&S[(size_t)b * NN * NN + idx]) = o;
    }
}

// ---------------------------------------------------------------------------
// P kernel (fp32 exact): P[row,m] = (|n-m| + sig*eps)/rowsum
// ---------------------------------------------------------------------------
__global__ __launch_bounds__(256) void p_kernel(
    const float* __restrict__ x, const float* __restrict__ Wsig,
    const float* __restrict__ eps, float* __restrict__ P)
{
    const int row = blockIdx.x;
    const int n = row & (NN - 1);
    const int tid = threadIdx.x;
    __shared__ float red[8];

    float part = x[(size_t)row * CC + tid] * Wsig[tid];
    #pragma unroll
    for (int o = 16; o > 0; o >>= 1) part += __shfl_xor_sync(0xffffffffu, part, o);
    if ((tid & 31) == 0) red[tid >> 5] = part;
    __syncthreads();
    float sig = red[0] + red[1] + red[2] + red[3] + red[4] + red[5] + red[6] + red[7];
    sig = fabsf(sig);
    __syncthreads();

    float4 e = *reinterpret_cast<const float4*>(&eps[(size_t)row * NN + tid * 4]);
    float ps = e.x + e.y + e.z + e.w;
    #pragma unroll
    for (int o = 16; o > 0; o >>= 1) ps += __shfl_xor_sync(0xffffffffu, ps, o);
    if ((tid & 31) == 0) red[tid >> 5] = ps;
    __syncthreads();
    float sum_eps = red[0] + red[1] + red[2] + red[3] + red[4] + red[5] + red[6] + red[7];

    float An = 0.5f * ((float)n * (float)(n + 1) +
                       (float)(NN - 1 - n) * (float)(NN - n));
    float inv = 1.0f / (An + sig * sum_eps);

    int m0 = tid * 4;
    float4 o4;
    o4.x = (fabsf((float)(n - (m0 + 0))) + sig * e.x) * inv;
    o4.y = (fabsf((float)(n - (m0 + 1))) + sig * e.y) * inv;
    o4.z = (fabsf((float)(n - (m0 + 2))) + sig * e.z) * inv;
    o4.w = (fabsf((float)(n - (m0 + 3))) + sig * e.w) * inv;
    *reinterpret_cast<float4*>(&P[(size_t)row * NN + m0]) = o4;
}

// ---------------------------------------------------------------------------
extern "C" void kernel_launch(void* const* d_in, const int* in_sizes, int n_in,
                              void* d_out, int out_size)
{
    const float* x   = (const float*)d_in[0];
    const float* Wq  = (const float*)d_in[1];
    const float* Wk  = (const float*)d_in[2];
    const float* Wv  = (const float*)d_in[3];
    const float* Ws  = (const float*)d_in[4];
    const float* eps = (const float*)d_in[5];
    float* out = (float*)d_out;

    float *QKV, *scores;
    cudaGetSymbolAddress((void**)&QKV, g_QKV);
    cudaGetSymbolAddress((void**)&scores, g_scores);

    // one-time side-stream + events for the P fork (no device allocation)
    static cudaStream_t s_p = nullptr;
    static cudaEvent_t ev_fork = nullptr, ev_join = nullptr;
    if (s_p == nullptr) {
        cudaStreamCreateWithFlags(&s_p, cudaStreamNonBlocking);
        cudaEventCreateWithFlags(&ev_fork, cudaEventDisableTiming);
        cudaEventCreateWithFlags(&ev_join, cudaEventDisableTiming);
    }

    const int SMEM_NMAJ = (3 * 128 * 36 + 3 * 32 * 264) * sizeof(float);  // 156,672
    const int SMEM_KMAJ = (3 * 128 * 36 + 3 * 256 * 36) * sizeof(float);  // 165,888
    cudaFuncSetAttribute((void*)mma_gemm<true,  true,  true,  true,  true >,
                         cudaFuncAttributeMaxDynamicSharedMemorySize, SMEM_NMAJ);
    cudaFuncSetAttribute((void*)mma_gemm<false, false, false, false, false>,
                         cudaFuncAttributeMaxDynamicSharedMemorySize, SMEM_KMAJ);
    cudaFuncSetAttribute((void*)mma_gemm<true,  false, true,  false, false>,
                         cudaFuncAttributeMaxDynamicSharedMemorySize, SMEM_NMAJ);

    const long long QKV_SZ = (long long)BB * NN * CC;

    // fork: P runs concurrently with the whole attention chain
    cudaEventRecord(ev_fork, 0);
    cudaStreamWaitEvent(s_p, ev_fork, 0);
    p_kernel<<<BB * NN, 256, 0, s_p>>>(x, Ws, eps, out + OFF_P);
    cudaEventRecord(ev_join, s_p);

    // 1) Q/K/V = round(x) @ round(W) — one launch, z picks the projection
    mma_gemm<true, true, true, true, true>
        <<<dim3(1, (BB * NN) / 128, 3), 256, SMEM_NMAJ>>>(
        x, Wq, Wk, Wv, QKV, CC, CC, CC, 1.0f, 0, 0, QKV_SZ);

    // 2) scores_b = Q_b @ K_b^T / 16
    mma_gemm<false, false, false, false, false>
        <<<dim3(NN / 256, NN / 128, BB), 256, SMEM_KMAJ>>>(
        QKV, QKV + QKV_SZ, nullptr, nullptr, scores, CC, CC, NN, 1.0f / 16.0f,
        (long long)NN * CC, (long long)NN * CC, (long long)NN * NN);

    // 3) softmax over batch dim: exact S -> out
    batch_softmax_kernel<<<(NN * NN) / 1024, 256>>>(scores, out + OFF_S);

    // 4) Z_b = round(S_b) @ V_b  (V consumed N-major, already rounded)
    mma_gemm<true, false, true, false, false>
        <<<dim3(1, NN / 128, BB), 256, SMEM_NMAJ>>>(
        out + OFF_S, QKV + 2 * QKV_SZ, nullptr, nullptr, out + OFF_Z,
        NN, CC, CC, 1.0f,
        (long long)NN * NN, (long long)NN * CC, (long long)NN * CC);

    // join P back into the main stream
    cudaStreamWaitEvent(0, ev_join, 0);
}

// round 8
// speedup vs baseline: 1.0003x; 1.0003x over previous
#include <cuda_runtime.h>
#include <cstdint>

// ---------------------------------------------------------------------------
// AnomalyAttention B=16, N=1024, C=256 — mma.sync tf32, 128x256 CTA tiles,
// P overlapped on a forked stream.
// Outputs: Z [B,N,C] | P [B,N,N] | S [B,N,N]
// ---------------------------------------------------------------------------

#define BB 16
#define NN 1024
#define CC 256

static const long long OFF_Z = 0;
static const long long OFF_P = (long long)BB * NN * CC;
static const long long OFF_S = OFF_P + (long long)BB * NN * NN;

__device__ float g_QKV[(size_t)3 * BB * NN * CC];     // Q|K|V (tf32-rounded)
__device__ float g_scores[(size_t)BB * NN * NN];      // raw scores

// ---------------------------------------------------------------------------
__device__ __forceinline__ uint32_t smem_u32(const void* p) {
    uint32_t a;
    asm("{ .reg .u64 t; cvta.to.shared.u64 t, %1; cvt.u32.u64 %0, t; }"
        : "=r"(a) : "l"(p));
    return a;
}
__device__ __forceinline__ float tf32r(float x) {
    float y; asm("cvt.rna.tf32.f32 %0, %1;" : "=f"(y) : "f"(x)); return y;
}
__device__ __forceinline__ uint32_t tf32u(uint32_t x) {
    float y = tf32r(__uint_as_float(x)); return __float_as_uint(y);
}

// ---------------------------------------------------------------------------
// mma.sync tf32 GEMM, CTA tile 128x256, 256 threads = 8 warps (2M x 4N),
// warp tile 64x64, BK=32, 3-stage cp.async ring.
//   BNMAJ=false: C = alpha * A * B^T   (B [N,K] K-major, ldb=K)
//   BNMAJ=true : C = alpha * A * B     (B [K,N] N-major, ldb)
//   MULTIB: B selected from {B0,B1,B2} by blockIdx.z (shared A).
//   RA/RB: round fragments to tf32 (rna) in-register. RO: round outputs.
// Bank-conflict-free: A/B K-major pad 36 (bank (4g+t)%32 bijective);
// B N-major pad 264 (bank (8t+g)%32 bijective).
// ---------------------------------------------------------------------------
template <bool BNMAJ, bool MULTIB, bool RA, bool RB, bool RO>
__global__ __launch_bounds__(256, 1) void mma_gemm(
    const float* __restrict__ A, const float* __restrict__ B0,
    const float* __restrict__ B1, const float* __restrict__ B2,
    float* __restrict__ C,
    int K, int ldb, int ldc, float alpha,
    long long sA, long long sB, long long sC)
{
    constexpr int BM = 128, BN = 256, BK = 32, PAD = 36, PADN = 264;
    constexpr int ASTG = BM * PAD;                        // 4608 floats
    constexpr int BSTG = BNMAJ ? BK * PADN : BN * PAD;    // 8448 / 9216
    extern __shared__ float sm[];
    float* As = sm;                  // [3][ASTG]
    float* Bs = sm + 3 * ASTG;       // [3][BSTG]

    const int z = blockIdx.z;
    const float* B = MULTIB ? (z == 0 ? B0 : (z == 1 ? B1 : B2))
                            : B0 + (long long)z * sB;
    A += (long long)z * sA;
    C += (long long)z * sC;

    const int tid = threadIdx.x, lane = tid & 31, wid = tid >> 5;
    const int wm = wid >> 2, wn = wid & 3;               // 2 x 4 warp grid
    const int g = lane >> 2, t = lane & 3;
    const long long arow0 = (long long)blockIdx.y * BM;
    const long long bcol0 = (long long)blockIdx.x * BN;

    const int nch = K / BK;

    auto issue = [&](int j) {
        if (j < nch) {
            const int st = j % 3;
            float* as = As + st * ASTG;
            float* bs = Bs + st * BSTG;
            #pragma unroll
            for (int i = 0; i < 4; i++) {               // A: 1024 chunks of 16B
                const int ch = tid + 256 * i;
                const int row = ch >> 3, c16 = ch & 7;
                const uint32_t da = smem_u32(&as[row * PAD + c16 * 4]);
                const float* pa = A + (arow0 + row) * K + (long long)j * BK + c16 * 4;
                asm volatile("cp.async.cg.shared.global [%0], [%1], 16;"
                             :: "r"(da), "l"(pa) : "memory");
            }
            #pragma unroll
            for (int i = 0; i < 8; i++) {               // B: 2048 chunks of 16B
                const int ch = tid + 256 * i;
                if (BNMAJ) {   // 32 k-rows x 64 chunks
                    const int row = ch >> 6, c4 = (ch & 63) * 4;
                    const uint32_t db = smem_u32(&bs[row * PADN + c4]);
                    const float* pb = B + ((long long)j * BK + row) * ldb + bcol0 + c4;
                    asm volatile("cp.async.cg.shared.global [%0], [%1], 16;"
                                 :: "r"(db), "l"(pb) : "memory");
                } else {       // 256 n-rows x 8 chunks
                    const int row = ch >> 3, c16 = ch & 7;
                    const uint32_t db = smem_u32(&bs[row * PAD + c16 * 4]);
                    const float* pb = B + (bcol0 + row) * ldb + (long long)j * BK + c16 * 4;
                    asm volatile("cp.async.cg.shared.global [%0], [%1], 16;"
                                 :: "r"(db), "l"(pb) : "memory");
                }
            }
        }
        asm volatile("cp.async.commit_group;" ::: "memory");
    };

    float acc[4][8][4];
    #pragma unroll
    for (int i = 0; i < 4; i++)
        #pragma unroll
        for (int jn = 0; jn < 8; jn++)
            #pragma unroll
            for (int r = 0; r < 4; r++) acc[i][jn][r] = 0.f;

    issue(0);
    issue(1);

    for (int j = 0; j < nch; j++) {
        if (j == nch - 1) asm volatile("cp.async.wait_group 0;" ::: "memory");
        else              asm volatile("cp.async.wait_group 1;" ::: "memory");
        __syncthreads();
        issue(j + 2);

        const float* a_ = As + (j % 3) * ASTG;
        const float* b_ = Bs + (j % 3) * BSTG;

        #pragma unroll
        for (int ks = 0; ks < 4; ks++) {
            uint32_t af[4][4], bf[8][2];
            #pragma unroll
            for (int mt = 0; mt < 4; mt++) {
                const int r = wm * 64 + mt * 16 + g;
                const int c = ks * 8 + t;
                af[mt][0] = __float_as_uint(a_[r * PAD + c]);
                af[mt][1] = __float_as_uint(a_[(r + 8) * PAD + c]);
                af[mt][2] = __float_as_uint(a_[r * PAD + c + 4]);
                af[mt][3] = __float_as_uint(a_[(r + 8) * PAD + c + 4]);
                if (RA) {
                    af[mt][0] = tf32u(af[mt][0]); af[mt][1] = tf32u(af[mt][1]);
                    af[mt][2] = tf32u(af[mt][2]); af[mt][3] = tf32u(af[mt][3]);
                }
            }
            #pragma unroll
            for (int nt = 0; nt < 8; nt++) {
                const int n = wn * 64 + nt * 8 + g;
                if (BNMAJ) {
                    bf[nt][0] = __float_as_uint(b_[(ks * 8 + t) * PADN + n]);
                    bf[nt][1] = __float_as_uint(b_[(ks * 8 + t + 4) * PADN + n]);
                } else {
                    bf[nt][0] = __float_as_uint(b_[n * PAD + ks * 8 + t]);
                    bf[nt][1] = __float_as_uint(b_[n * PAD + ks * 8 + t + 4]);
                }
                if (RB) { bf[nt][0] = tf32u(bf[nt][0]); bf[nt][1] = tf32u(bf[nt][1]); }
            }
            #pragma unroll
            for (int mt = 0; mt < 4; mt++)
                #pragma unroll
                for (int nt = 0; nt < 8; nt++)
                    asm volatile(
                        "mma.sync.aligned.m16n8k8.row.col.f32.tf32.tf32.f32 "
                        "{%0,%1,%2,%3}, {%4,%5,%6,%7}, {%8,%9}, {%0,%1,%2,%3};"
                        : "+f"(acc[mt][nt][0]), "+f"(acc[mt][nt][1]),
                          "+f"(acc[mt][nt][2]), "+f"(acc[mt][nt][3])
                        : "r"(af[mt][0]), "r"(af[mt][1]), "r"(af[mt][2]), "r"(af[mt][3]),
                          "r"(bf[nt][0]), "r"(bf[nt][1]));
        }
    }

    #pragma unroll
    for (int mt = 0; mt < 4; mt++) {
        const long long gr = arow0 + wm * 64 + mt * 16 + g;
        #pragma unroll
        for (int nt = 0; nt < 8; nt++) {
            const long long gc = bcol0 + wn * 64 + nt * 8 + 2 * t;
            float2 v0 = make_float2(acc[mt][nt][0] * alpha, acc[mt][nt][1] * alpha);
            float2 v1 = make_float2(acc[mt][nt][2] * alpha, acc[mt][nt][3] * alpha);
            if (RO) {
                v0.x = tf32r(v0.x); v0.y = tf32r(v0.y);
                v1.x = tf32r(v1.x); v1.y = tf32r(v1.y);
            }
            *reinterpret_cast<float2*>(&C[gr * ldc + gc])       = v0;
            *reinterpret_cast<float2*>(&C[(gr + 8) * ldc + gc]) = v1;
        }
    }
}

// ---------------------------------------------------------------------------
// softmax over batch dim (axis=0), float4-vectorized: exact S -> out
// ---------------------------------------------------------------------------
__global__ __launch_bounds__(256) void batch_softmax_kernel(
    const float* __restrict__ scores, float* __restrict__ S)
{
    size_t idx = ((size_t)blockIdx.x * blockDim.x + threadIdx.x) * 4;
    float4 v[BB];
    float4 mx = make_float4(-1e30f, -1e30f, -1e30f, -1e30f);
    #pragma unroll
    for (int b = 0; b < BB; b++) {
        v[b] = *reinterpret_cast<const float4*>(&scores[(size_t)b * NN * NN + idx]);
        mx.x = fmaxf(mx.x, v[b].x); mx.y = fmaxf(mx.y, v[b].y);
        mx.z = fmaxf(mx.z, v[b].z); mx.w = fmaxf(mx.w, v[b].w);
    }
    float4 s = make_float4(0.f, 0.f, 0.f, 0.f);
    #pragma unroll
    for (int b = 0; b < BB; b++) {
        v[b].x = __expf(v[b].x - mx.x); s.x += v[b].x;
        v[b].y = __expf(v[b].y - mx.y); s.y += v[b].y;
        v[b].z = __expf(v[b].z - mx.z); s.z += v[b].z;
        v[b].w = __expf(v[b].w - mx.w); s.w += v[b].w;
    }
    const float4 inv = make_float4(1.f / s.x, 1.f / s.y, 1.f / s.z, 1.f / s.w);
    #pragma unroll
    for (int b = 0; b < BB; b++) {
        float4 o = make_float4(v[b].x * inv.x, v[b].y * inv.y,
                               v[b].z * inv.z, v[b].w * inv.w);
        *reinterpret_cast<float4*>(&S[(size_t)b * NN * NN + idx]) = o;
    }
}

// ---------------------------------------------------------------------------
// P kernel (fp32 exact): P[row,m] = (|n-m| + sig*eps)/rowsum
// ---------------------------------------------------------------------------
__global__ __launch_bounds__(256) void p_kernel(
    const float* __restrict__ x, const float* __restrict__ Wsig,
    const float* __restrict__ eps, float* __restrict__ P)
{
    const int row = blockIdx.x;
    const int n = row & (NN - 1);
    const int tid = threadIdx.x;
    __shared__ float red[8];

    float part = x[(size_t)row * CC + tid] * Wsig[tid];
    #pragma unroll
    for (int o = 16; o > 0; o >>= 1) part += __shfl_xor_sync(0xffffffffu, part, o);
    if ((tid & 31) == 0) red[tid >> 5] = part;
    __syncthreads();
    float sig = red[0] + red[1] + red[2] + red[3] + red[4] + red[5] + red[6] + red[7];
    sig = fabsf(sig);
    __syncthreads();

    float4 e = *reinterpret_cast<const float4*>(&eps[(size_t)row * NN + tid * 4]);
    float ps = e.x + e.y + e.z + e.w;
    #pragma unroll
    for (int o = 16; o > 0; o >>= 1) ps += __shfl_xor_sync(0xffffffffu, ps, o);
    if ((tid & 31) == 0) red[tid >> 5] = ps;
    __syncthreads();
    float sum_eps = red[0] + red[1] + red[2] + red[3] + red[4] + red[5] + red[6] + red[7];

    float An = 0.5f * ((float)n * (float)(n + 1) +
                       (float)(NN - 1 - n) * (float)(NN - n));
    float inv = 1.0f / (An + sig * sum_eps);

    int m0 = tid * 4;
    float4 o4;
    o4.x = (fabsf((float)(n - (m0 + 0))) + sig * e.x) * inv;
    o4.y = (fabsf((float)(n - (m0 + 1))) + sig * e.y) * inv;
    o4.z = (fabsf((float)(n - (m0 + 2))) + sig * e.z) * inv;
    o4.w = (fabsf((float)(n - (m0 + 3))) + sig * e.w) * inv;
    *reinterpret_cast<float4*>(&P[(size_t)row * NN + m0]) = o4;
}

// ---------------------------------------------------------------------------
extern "C" void kernel_launch(void* const* d_in, const int* in_sizes, int n_in,
                              void* d_out, int out_size)
{
    const float* x   = (const float*)d_in[0];
    const float* Wq  = (const float*)d_in[1];
    const float* Wk  = (const float*)d_in[2];
    const float* Wv  = (const float*)d_in[3];
    const float* Ws  = (const float*)d_in[4];
    const float* eps = (const float*)d_in[5];
    float* out = (float*)d_out;

    float *QKV, *scores;
    cudaGetSymbolAddress((void**)&QKV, g_QKV);
    cudaGetSymbolAddress((void**)&scores, g_scores);

    // one-time side-stream + events for the P fork (no device allocation)
    static cudaStream_t s_p = nullptr;
    static cudaEvent_t ev_fork = nullptr, ev_join = nullptr;
    if (s_p == nullptr) {
        cudaStreamCreateWithFlags(&s_p, cudaStreamNonBlocking);
        cudaEventCreateWithFlags(&ev_fork, cudaEventDisableTiming);
        cudaEventCreateWithFlags(&ev_join, cudaEventDisableTiming);
    }

    const int SMEM_NMAJ = (3 * 128 * 36 + 3 * 32 * 264) * sizeof(float);  // 156,672
    const int SMEM_KMAJ = (3 * 128 * 36 + 3 * 256 * 36) * sizeof(float);  // 165,888
    cudaFuncSetAttribute((void*)mma_gemm<true,  true,  true,  true,  true >,
                         cudaFuncAttributeMaxDynamicSharedMemorySize, SMEM_NMAJ);
    cudaFuncSetAttribute((void*)mma_gemm<false, false, false, false, false>,
                         cudaFuncAttributeMaxDynamicSharedMemorySize, SMEM_KMAJ);
    cudaFuncSetAttribute((void*)mma_gemm<true,  false, true,  false, false>,
                         cudaFuncAttributeMaxDynamicSharedMemorySize, SMEM_NMAJ);

    const long long QKV_SZ = (long long)BB * NN * CC;

    // fork: P runs concurrently with the whole attention chain
    cudaEventRecord(ev_fork, 0);
    cudaStreamWaitEvent(s_p, ev_fork, 0);
    p_kernel<<<BB * NN, 256, 0, s_p>>>(x, Ws, eps, out + OFF_P);
    cudaEventRecord(ev_join, s_p);

    // 1) Q/K/V = round(x) @ round(W) — one launch, z picks the projection
    mma_gemm<true, true, true, true, true>
        <<<dim3(1, (BB * NN) / 128, 3), 256, SMEM_NMAJ>>>(
        x, Wq, Wk, Wv, QKV, CC, CC, CC, 1.0f, 0, 0, QKV_SZ);

    // 2) scores_b = Q_b @ K_b^T / 16
    mma_gemm<false, false, false, false, false>
        <<<dim3(NN / 256, NN / 128, BB), 256, SMEM_KMAJ>>>(
        QKV, QKV + QKV_SZ, nullptr, nullptr, scores, CC, CC, NN, 1.0f / 16.0f,
        (long long)NN * CC, (long long)NN * CC, (long long)NN * NN);

    // 3) softmax over batch dim: exact S -> out
    batch_softmax_kernel<<<(NN * NN) / 1024, 256>>>(scores, out + OFF_S);

    // 4) Z_b = round(S_b) @ V_b  (V consumed N-major, already rounded)
    mma_gemm<true, false, true, false, false>
        <<<dim3(1, NN / 128, BB), 256, SMEM_NMAJ>>>(
        out + OFF_S, QKV + 2 * QKV_SZ, nullptr, nullptr, out + OFF_Z,
        NN, CC, CC, 1.0f,
        (long long)NN * NN, (long long)NN * CC, (long long)NN * CC);

    // join P back into the main stream
    cudaStreamWaitEvent(0, ev_join, 0);
}

// round 9
// speedup vs baseline: 1.0011x; 1.0008x over previous
#include <cuda_runtime.h>
#include <cstdint>

// ---------------------------------------------------------------------------
// AnomalyAttention B=16, N=1024, C=256 — mma.sync tf32, 128x256 CTA tiles,
// P overlapped on a forked stream.
// Outputs: Z [B,N,C] | P [B,N,N] | S [B,N,N]
// ---------------------------------------------------------------------------

#define BB 16
#define NN 1024
#define CC 256

static const long long OFF_Z = 0;
static const long long OFF_P = (long long)BB * NN * CC;
static const long long OFF_S = OFF_P + (long long)BB * NN * NN;

__device__ float g_QKV[(size_t)3 * BB * NN * CC];     // Q|K|V (tf32-rounded)
__device__ float g_scores[(size_t)BB * NN * NN];      // raw scores

// ---------------------------------------------------------------------------
__device__ __forceinline__ uint32_t smem_u32(const void* p) {
    uint32_t a;
    asm("{ .reg .u64 t; cvta.to.shared.u64 t, %1; cvt.u32.u64 %0, t; }"
        : "=r"(a) : "l"(p));
    return a;
}
__device__ __forceinline__ float tf32r(float x) {
    float y; asm("cvt.rna.tf32.f32 %0, %1;" : "=f"(y) : "f"(x)); return y;
}
__device__ __forceinline__ uint32_t tf32u(uint32_t x) {
    float y = tf32r(__uint_as_float(x)); return __float_as_uint(y);
}

// ---------------------------------------------------------------------------
// mma.sync tf32 GEMM, CTA tile 128x256, 256 threads = 8 warps (2M x 4N),
// warp tile 64x64, BK=32, 3-stage cp.async ring.
//   BNMAJ=false: C = alpha * A * B^T   (B [N,K] K-major, ldb=K)
//   BNMAJ=true : C = alpha * A * B     (B [K,N] N-major, ldb)
//   MULTIB: B selected from {B0,B1,B2} by blockIdx.z (shared A).
//   RA/RB: round fragments to tf32 (rna) in-register. RO: round outputs.
// Bank-conflict-free: A/B K-major pad 36 (bank (4g+t)%32 bijective);
// B N-major pad 264 (bank (8t+g)%32 bijective).
// ---------------------------------------------------------------------------
template <bool BNMAJ, bool MULTIB, bool RA, bool RB, bool RO>
__global__ __launch_bounds__(256, 1) void mma_gemm(
    const float* __restrict__ A, const float* __restrict__ B0,
    const float* __restrict__ B1, const float* __restrict__ B2,
    float* __restrict__ C,
    int K, int ldb, int ldc, float alpha,
    long long sA, long long sB, long long sC)
{
    constexpr int BM = 128, BN = 256, BK = 32, PAD = 36, PADN = 264;
    constexpr int ASTG = BM * PAD;                        // 4608 floats
    constexpr int BSTG = BNMAJ ? BK * PADN : BN * PAD;    // 8448 / 9216
    extern __shared__ float sm[];
    float* As = sm;                  // [3][ASTG]
    float* Bs = sm + 3 * ASTG;       // [3][BSTG]

    const int z = blockIdx.z;
    const float* B = MULTIB ? (z == 0 ? B0 : (z == 1 ? B1 : B2))
                            : B0 + (long long)z * sB;
    A += (long long)z * sA;
    C += (long long)z * sC;

    const int tid = threadIdx.x, lane = tid & 31, wid = tid >> 5;
    const int wm = wid >> 2, wn = wid & 3;               // 2 x 4 warp grid
    const int g = lane >> 2, t = lane & 3;
    const long long arow0 = (long long)blockIdx.y * BM;
    const long long bcol0 = (long long)blockIdx.x * BN;

    const int nch = K / BK;

    auto issue = [&](int j) {
        if (j < nch) {
            const int st = j % 3;
            float* as = As + st * ASTG;
            float* bs = Bs + st * BSTG;
            #pragma unroll
            for (int i = 0; i < 4; i++) {               // A: 1024 chunks of 16B
                const int ch = tid + 256 * i;
                const int row = ch >> 3, c16 = ch & 7;
                const uint32_t da = smem_u32(&as[row * PAD + c16 * 4]);
                const float* pa = A + (arow0 + row) * K + (long long)j * BK + c16 * 4;
                asm volatile("cp.async.cg.shared.global [%0], [%1], 16;"
                             :: "r"(da), "l"(pa) : "memory");
            }
            #pragma unroll
            for (int i = 0; i < 8; i++) {               // B: 2048 chunks of 16B
                const int ch = tid + 256 * i;
                if (BNMAJ) {   // 32 k-rows x 64 chunks
                    const int row = ch >> 6, c4 = (ch & 63) * 4;
                    const uint32_t db = smem_u32(&bs[row * PADN + c4]);
                    const float* pb = B + ((long long)j * BK + row) * ldb + bcol0 + c4;
                    asm volatile("cp.async.cg.shared.global [%0], [%1], 16;"
                                 :: "r"(db), "l"(pb) : "memory");
                } else {       // 256 n-rows x 8 chunks
                    const int row = ch >> 3, c16 = ch & 7;
                    const uint32_t db = smem_u32(&bs[row * PAD + c16 * 4]);
                    const float* pb = B + (bcol0 + row) * ldb + (long long)j * BK + c16 * 4;
                    asm volatile("cp.async.cg.shared.global [%0], [%1], 16;"
                                 :: "r"(db), "l"(pb) : "memory");
                }
            }
        }
        asm volatile("cp.async.commit_group;" ::: "memory");
    };

    float acc[4][8][4];
    #pragma unroll
    for (int i = 0; i < 4; i++)
        #pragma unroll
        for (int jn = 0; jn < 8; jn++)
            #pragma unroll
            for (int r = 0; r < 4; r++) acc[i][jn][r] = 0.f;

    issue(0);
    issue(1);

    for (int j = 0; j < nch; j++) {
        if (j == nch - 1) asm volatile("cp.async.wait_group 0;" ::: "memory");
        else              asm volatile("cp.async.wait_group 1;" ::: "memory");
        __syncthreads();
        issue(j + 2);

        const float* a_ = As + (j % 3) * ASTG;
        const float* b_ = Bs + (j % 3) * BSTG;

        #pragma unroll
        for (int ks = 0; ks < 4; ks++) {
            uint32_t af[4][4], bf[8][2];
            #pragma unroll
            for (int mt = 0; mt < 4; mt++) {
                const int r = wm * 64 + mt * 16 + g;
                const int c = ks * 8 + t;
                af[mt][0] = __float_as_uint(a_[r * PAD + c]);
                af[mt][1] = __float_as_uint(a_[(r + 8) * PAD + c]);
                af[mt][2] = __float_as_uint(a_[r * PAD + c + 4]);
                af[mt][3] = __float_as_uint(a_[(r + 8) * PAD + c + 4]);
                if (RA) {
                    af[mt][0] = tf32u(af[mt][0]); af[mt][1] = tf32u(af[mt][1]);
                    af[mt][2] = tf32u(af[mt][2]); af[mt][3] = tf32u(af[mt][3]);
                }
            }
            #pragma unroll
            for (int nt = 0; nt < 8; nt++) {
                const int n = wn * 64 + nt * 8 + g;
                if (BNMAJ) {
                    bf[nt][0] = __float_as_uint(b_[(ks * 8 + t) * PADN + n]);
                    bf[nt][1] = __float_as_uint(b_[(ks * 8 + t + 4) * PADN + n]);
                } else {
                    bf[nt][0] = __float_as_uint(b_[n * PAD + ks * 8 + t]);
                    bf[nt][1] = __float_as_uint(b_[n * PAD + ks * 8 + t + 4]);
                }
                if (RB) { bf[nt][0] = tf32u(bf[nt][0]); bf[nt][1] = tf32u(bf[nt][1]); }
            }
            #pragma unroll
            for (int mt = 0; mt < 4; mt++)
                #pragma unroll
                for (int nt = 0; nt < 8; nt++)
                    asm volatile(
                        "mma.sync.aligned.m16n8k8.row.col.f32.tf32.tf32.f32 "
                        "{%0,%1,%2,%3}, {%4,%5,%6,%7}, {%8,%9}, {%0,%1,%2,%3};"
                        : "+f"(acc[mt][nt][0]), "+f"(acc[mt][nt][1]),
                          "+f"(acc[mt][nt][2]), "+f"(acc[mt][nt][3])
                        : "r"(af[mt][0]), "r"(af[mt][1]), "r"(af[mt][2]), "r"(af[mt][3]),
                          "r"(bf[nt][0]), "r"(bf[nt][1]));
        }
    }

    #pragma unroll
    for (int mt = 0; mt < 4; mt++) {
        const long long gr = arow0 + wm * 64 + mt * 16 + g;
        #pragma unroll
        for (int nt = 0; nt < 8; nt++) {
            const long long gc = bcol0 + wn * 64 + nt * 8 + 2 * t;
            float2 v0 = make_float2(acc[mt][nt][0] * alpha, acc[mt][nt][1] * alpha);
            float2 v1 = make_float2(acc[mt][nt][2] * alpha, acc[mt][nt][3] * alpha);
            if (RO) {
                v0.x = tf32r(v0.x); v0.y = tf32r(v0.y);
                v1.x = tf32r(v1.x); v1.y = tf32r(v1.y);
            }
            *reinterpret_cast<float2*>(&C[gr * ldc + gc])       = v0;
            *reinterpret_cast<float2*>(&C[(gr + 8) * ldc + gc]) = v1;
        }
    }
}

// ---------------------------------------------------------------------------
// softmax over batch dim (axis=0), float4-vectorized: exact S -> out
// ---------------------------------------------------------------------------
__global__ __launch_bounds__(256) void batch_softmax_kernel(
    const float* __restrict__ scores, float* __restrict__ S)
{
    size_t idx = ((size_t)blockIdx.x * blockDim.x + threadIdx.x) * 4;
    float4 v[BB];
    float4 mx = make_float4(-1e30f, -1e30f, -1e30f, -1e30f);
    #pragma unroll
    for (int b = 0; b < BB; b++) {
        v[b] = *reinterpret_cast<const float4*>(&scores[(size_t)b * NN * NN + idx]);
        mx.x = fmaxf(mx.x, v[b].x); mx.y = fmaxf(mx.y, v[b].y);
        mx.z = fmaxf(mx.z, v[b].z); mx.w = fmaxf(mx.w, v[b].w);
    }
    float4 s = make_float4(0.f, 0.f, 0.f, 0.f);
    #pragma unroll
    for (int b = 0; b < BB; b++) {
        v[b].x = __expf(v[b].x - mx.x); s.x += v[b].x;
        v[b].y = __expf(v[b].y - mx.y); s.y += v[b].y;
        v[b].z = __expf(v[b].z - mx.z); s.z += v[b].z;
        v[b].w = __expf(v[b].w - mx.w); s.w += v[b].w;
    }
    const float4 inv = make_float4(1.f / s.x, 1.f / s.y, 1.f / s.z, 1.f / s.w);
    #pragma unroll
    for (int b = 0; b < BB; b++) {
        float4 o = make_float4(v[b].x * inv.x, v[b].y * inv.y,
                               v[b].z * inv.z, v[b].w * inv.w);
        *reinterpret_cast<float4*>(&S[(size_t)b * NN * NN + idx]) = o;
    }
}

// ---------------------------------------------------------------------------
// P kernel (fp32 exact): P[row,m] = (|n-m| + sig*eps)/rowsum
// ---------------------------------------------------------------------------
__global__ __launch_bounds__(256) void p_kernel(
    const float* __restrict__ x, const float* __restrict__ Wsig,
    const float* __restrict__ eps, float* __restrict__ P)
{
    const int row = blockIdx.x;
    const int n = row & (NN - 1);
    const int tid = threadIdx.x;
    __shared__ float red[8];

    float part = x[(size_t)row * CC + tid] * Wsig[tid];
    #pragma unroll
    for (int o = 16; o > 0; o >>= 1) part += __shfl_xor_sync(0xffffffffu, part, o);
    if ((tid & 31) == 0) red[tid >> 5] = part;
    __syncthreads();
    float sig = red[0] + red[1] + red[2] + red[3] + red[4] + red[5] + red[6] + red[7];
    sig = fabsf(sig);
    __syncthreads();

    float4 e = *reinterpret_cast<const float4*>(&eps[(size_t)row * NN + tid * 4]);
    float ps = e.x + e.y + e.z + e.w;
    #pragma unroll
    for (int o = 16; o > 0; o >>= 1) ps += __shfl_xor_sync(0xffffffffu, ps, o);
    if ((tid & 31) == 0) red[tid >> 5] = ps;
    __syncthreads();
    float sum_eps = red[0] + red[1] + red[2] + red[3] + red[4] + red[5] + red[6] + red[7];

    float An = 0.5f * ((float)n * (float)(n + 1) +
                       (float)(NN - 1 - n) * (float)(NN - n));
    float inv = 1.0f / (An + sig * sum_eps);

    int m0 = tid * 4;
    float4 o4;
    o4.x = (fabsf((float)(n - (m0 + 0))) + sig * e.x) * inv;
    o4.y = (fabsf((float)(n - (m0 + 1))) + sig * e.y) * inv;
    o4.z = (fabsf((float)(n - (m0 + 2))) + sig * e.z) * inv;
    o4.w = (fabsf((float)(n - (m0 + 3))) + sig * e.w) * inv;
    *reinterpret_cast<float4*>(&P[(size_t)row * NN + m0]) = o4;
}

// ---------------------------------------------------------------------------
extern "C" void kernel_launch(void* const* d_in, const int* in_sizes, int n_in,
                              void* d_out, int out_size)
{
    const float* x   = (const float*)d_in[0];
    const float* Wq  = (const float*)d_in[1];
    const float* Wk  = (const float*)d_in[2];
    const float* Wv  = (const float*)d_in[3];
    const float* Ws  = (const float*)d_in[4];
    const float* eps = (const float*)d_in[5];
    float* out = (float*)d_out;

    float *QKV, *scores;
    cudaGetSymbolAddress((void**)&QKV, g_QKV);
    cudaGetSymbolAddress((void**)&scores, g_scores);

    // one-time side-stream + events for the P fork (no device allocation)
    static cudaStream_t s_p = nullptr;
    static cudaEvent_t ev_fork = nullptr, ev_join = nullptr;
    if (s_p == nullptr) {
        cudaStreamCreateWithFlags(&s_p, cudaStreamNonBlocking);
        cudaEventCreateWithFlags(&ev_fork, cudaEventDisableTiming);
        cudaEventCreateWithFlags(&ev_join, cudaEventDisableTiming);
    }

    const int SMEM_NMAJ = (3 * 128 * 36 + 3 * 32 * 264) * sizeof(float);  // 156,672
    const int SMEM_KMAJ = (3 * 128 * 36 + 3 * 256 * 36) * sizeof(float);  // 165,888
    cudaFuncSetAttribute((void*)mma_gemm<true,  true,  true,  true,  true >,
                         cudaFuncAttributeMaxDynamicSharedMemorySize, SMEM_NMAJ);
    cudaFuncSetAttribute((void*)mma_gemm<false, false, false, false, false>,
                         cudaFuncAttributeMaxDynamicSharedMemorySize, SMEM_KMAJ);
    cudaFuncSetAttribute((void*)mma_gemm<true,  false, true,  false, false>,
                         cudaFuncAttributeMaxDynamicSharedMemorySize, SMEM_NMAJ);

    const long long QKV_SZ = (long long)BB * NN * CC;

    // fork: P runs concurrently with the whole attention chain
    cudaEventRecord(ev_fork, 0);
    cudaStreamWaitEvent(s_p, ev_fork, 0);
    p_kernel<<<BB * NN, 256, 0, s_p>>>(x, Ws, eps, out + OFF_P);
    cudaEventRecord(ev_join, s_p);

    // 1) Q/K/V = round(x) @ round(W) — one launch, z picks the projection
    mma_gemm<true, true, true, true, true>
        <<<dim3(1, (BB * NN) / 128, 3), 256, SMEM_NMAJ>>>(
        x, Wq, Wk, Wv, QKV, CC, CC, CC, 1.0f, 0, 0, QKV_SZ);

    // 2) scores_b = Q_b @ K_b^T / 16
    mma_gemm<false, false, false, false, false>
        <<<dim3(NN / 256, NN / 128, BB), 256, SMEM_KMAJ>>>(
        QKV, QKV + QKV_SZ, nullptr, nullptr, scores, CC, CC, NN, 1.0f / 16.0f,
        (long long)NN * CC, (long long)NN * CC, (long long)NN * NN);

    // 3) softmax over batch dim: exact S -> out
    batch_softmax_kernel<<<(NN * NN) / 1024, 256>>>(scores, out + OFF_S);

    // 4) Z_b = round(S_b) @ V_b  (V consumed N-major, already rounded)
    mma_gemm<true, false, true, false, false>
        <<<dim3(1, NN / 128, BB), 256, SMEM_NMAJ>>>(
        out + OFF_S, QKV + 2 * QKV_SZ, nullptr, nullptr, out + OFF_Z,
        NN, CC, CC, 1.0f,
        (long long)NN * NN, (long long)NN * CC, (long long)NN * CC);

    // join P back into the main stream
    cudaStreamWaitEvent(0, ev_join, 0);
}

// round 10
// speedup vs baseline: 1.1872x; 1.1859x over previous
#include <cuda_runtime.h>
#include <cuda_fp16.h>
#include <cstdint>

// ---------------------------------------------------------------------------
// AnomalyAttention B=16, N=1024, C=256
// QKV: mma.sync tf32 (fp32 in, fp16 out). scores/Z: mma.sync fp16 m16n8k16.
// Outputs: Z [B,N,C] | P [B,N,N] | S [B,N,N]
// ---------------------------------------------------------------------------

#define BB 16
#define NN 1024
#define CC 256

static const long long OFF_Z = 0;
static const long long OFF_P = (long long)BB * NN * CC;
static const long long OFF_S = OFF_P + (long long)BB * NN * NN;

__device__ __half g_QKVh[(size_t)3 * BB * NN * CC];   // Q|K|V fp16, K-major
__device__ __half g_Vth[(size_t)BB * NN * CC];        // V^T fp16 [C,N] per batch
__device__ __half g_Sh[(size_t)BB * NN * NN];         // fp16 S for Z GEMM
__device__ float  g_scores[(size_t)BB * NN * NN];     // raw scores fp32

// ---------------------------------------------------------------------------
__device__ __forceinline__ uint32_t smem_u32(const void* p) {
    uint32_t a;
    asm("{ .reg .u64 t; cvta.to.shared.u64 t, %1; cvt.u32.u64 %0, t; }"
        : "=r"(a) : "l"(p));
    return a;
}
__device__ __forceinline__ float tf32r(float x) {
    float y; asm("cvt.rna.tf32.f32 %0, %1;" : "=f"(y) : "f"(x)); return y;
}
__device__ __forceinline__ uint32_t tf32u(uint32_t x) {
    float y = tf32r(__uint_as_float(x)); return __float_as_uint(y);
}

// ---------------------------------------------------------------------------
// QKV GEMM (tf32): C_h = round_f16( round_tf32(A) @ round_tf32(B) )
// A = x [M,K=256] fp32 K-major (shared across z); B = W_z [K,N] fp32 N-major.
// CTA 128x256, 256 thr, 8 warps (2Mx4N), warp 64x64, BK=32, 3-stage ring.
// Output fp16 K-major [M, 256].
// ---------------------------------------------------------------------------
__global__ __launch_bounds__(256, 1) void qkv_gemm(
    const float* __restrict__ A, const float* __restrict__ B0,
    const float* __restrict__ B1, const float* __restrict__ B2,
    __half* __restrict__ C, long long sC)
{
    constexpr int BM = 128, BN = 256, BK = 32, K = CC, PAD = 36, PADN = 264;
    constexpr int ASTG = BM * PAD;
    constexpr int BSTG = BK * PADN;
    extern __shared__ float sm[];
    float* As = sm;
    float* Bs = sm + 3 * ASTG;

    const int z = blockIdx.z;
    const float* B = (z == 0 ? B0 : (z == 1 ? B1 : B2));
    C += (long long)z * sC;

    const int tid = threadIdx.x, lane = tid & 31, wid = tid >> 5;
    const int wm = wid >> 2, wn = wid & 3;
    const int g = lane >> 2, t = lane & 3;
    const long long arow0 = (long long)blockIdx.y * BM;
    const int nch = K / BK;

    auto issue = [&](int j) {
        if (j < nch) {
            const int st = j % 3;
            float* as = As + st * ASTG;
            float* bs = Bs + st * BSTG;
            #pragma unroll
            for (int i = 0; i < 4; i++) {               // A: 1024 16B chunks
                const int ch = tid + 256 * i;
                const int row = ch >> 3, c16 = ch & 7;
                asm volatile("cp.async.cg.shared.global [%0], [%1], 16;"
                    :: "r"(smem_u32(&as[row * PAD + c16 * 4])),
                       "l"(A + (arow0 + row) * K + (long long)j * BK + c16 * 4)
                    : "memory");
            }
            #pragma unroll
            for (int i = 0; i < 8; i++) {               // B: 32 k-rows x 64 chunks
                const int ch = tid + 256 * i;
                const int row = ch >> 6, c4 = (ch & 63) * 4;
                asm volatile("cp.async.cg.shared.global [%0], [%1], 16;"
                    :: "r"(smem_u32(&bs[row * PADN + c4])),
                       "l"(B + ((long long)j * BK + row) * BN + c4)
                    : "memory");
            }
        }
        asm volatile("cp.async.commit_group;" ::: "memory");
    };

    float acc[4][8][4];
    #pragma unroll
    for (int i = 0; i < 4; i++)
        #pragma unroll
        for (int jn = 0; jn < 8; jn++)
            #pragma unroll
            for (int r = 0; r < 4; r++) acc[i][jn][r] = 0.f;

    issue(0); issue(1);

    for (int j = 0; j < nch; j++) {
        if (j == nch - 1) asm volatile("cp.async.wait_group 0;" ::: "memory");
        else              asm volatile("cp.async.wait_group 1;" ::: "memory");
        __syncthreads();
        issue(j + 2);

        const float* a_ = As + (j % 3) * ASTG;
        const float* b_ = Bs + (j % 3) * BSTG;

        #pragma unroll
        for (int ks = 0; ks < 4; ks++) {
            uint32_t af[4][4], bf[8][2];
            #pragma unroll
            for (int mt = 0; mt < 4; mt++) {
                const int r = wm * 64 + mt * 16 + g;
                const int c = ks * 8 + t;
                af[mt][0] = tf32u(__float_as_uint(a_[r * PAD + c]));
                af[mt][1] = tf32u(__float_as_uint(a_[(r + 8) * PAD + c]));
                af[mt][2] = tf32u(__float_as_uint(a_[r * PAD + c + 4]));
                af[mt][3] = tf32u(__float_as_uint(a_[(r + 8) * PAD + c + 4]));
            }
            #pragma unroll
            for (int nt = 0; nt < 8; nt++) {
                const int n = wn * 64 + nt * 8 + g;
                bf[nt][0] = tf32u(__float_as_uint(b_[(ks * 8 + t) * PADN + n]));
                bf[nt][1] = tf32u(__float_as_uint(b_[(ks * 8 + t + 4) * PADN + n]));
            }
            #pragma unroll
            for (int mt = 0; mt < 4; mt++)
                #pragma unroll
                for (int nt = 0; nt < 8; nt++)
                    asm volatile(
                        "mma.sync.aligned.m16n8k8.row.col.f32.tf32.tf32.f32 "
                        "{%0,%1,%2,%3}, {%4,%5,%6,%7}, {%8,%9}, {%0,%1,%2,%3};"
                        : "+f"(acc[mt][nt][0]), "+f"(acc[mt][nt][1]),
                          "+f"(acc[mt][nt][2]), "+f"(acc[mt][nt][3])
                        : "r"(af[mt][0]), "r"(af[mt][1]), "r"(af[mt][2]), "r"(af[mt][3]),
                          "r"(bf[nt][0]), "r"(bf[nt][1]));
        }
    }

    #pragma unroll
    for (int mt = 0; mt < 4; mt++) {
        const long long gr = arow0 + wm * 64 + mt * 16 + g;
        #pragma unroll
        for (int nt = 0; nt < 8; nt++) {
            const long long gc = wn * 64 + nt * 8 + 2 * t;
            *reinterpret_cast<__half2*>(&C[gr * BN + gc]) =
                __floats2half2_rn(acc[mt][nt][0], acc[mt][nt][1]);
            *reinterpret_cast<__half2*>(&C[(gr + 8) * BN + gc]) =
                __floats2half2_rn(acc[mt][nt][2], acc[mt][nt][3]);
        }
    }
}

// ---------------------------------------------------------------------------
// fp16 GEMM: C(fp32) = alpha * A * B^T
// A [M,K] half K-major (lda=K), B [N,K] half K-major (ldb=K). K%32==0.
// CTA 128x256, 256 thr, warp 64x64, m16n8k16, BK=32 halves, 3-stage ring.
// smem rows padded to PITCH=20 u32-granules; fragment bank (20g+t)%32 bijective.
// ---------------------------------------------------------------------------
__global__ __launch_bounds__(256, 1) void mma_gemm_f16(
    const __half* __restrict__ A, const __half* __restrict__ B,
    float* __restrict__ C,
    int K, int ldc, float alpha, long long sA, long long sB, long long sC)
{
    constexpr int BM = 128, BN = 256, BK = 32, PITCH = 20;
    constexpr int ASTG = BM * PITCH;    // 2560 u32
    constexpr int BSTG = BN * PITCH;    // 5120 u32
    extern __shared__ uint32_t smh[];
    uint32_t* As = smh;
    uint32_t* Bs = smh + 3 * ASTG;

    const int z = blockIdx.z;
    A += (long long)z * sA;
    B += (long long)z * sB;
    C += (long long)z * sC;

    const int tid = threadIdx.x, lane = tid & 31, wid = tid >> 5;
    const int wm = wid >> 2, wn = wid & 3;
    const int g = lane >> 2, t = lane & 3;
    const long long arow0 = (long long)blockIdx.y * BM;
    const long long bcol0 = (long long)blockIdx.x * BN;
    const int nch = K / BK;

    auto issue = [&](int j) {
        if (j < nch) {
            const int st = j % 3;
            uint32_t* as = As + st * ASTG;
            uint32_t* bs = Bs + st * BSTG;
            #pragma unroll
            for (int i = 0; i < 2; i++) {               // A: 512 16B chunks
                const int ch = tid + 256 * i;
                const int row = ch >> 2, c16 = ch & 3;
                asm volatile("cp.async.cg.shared.global [%0], [%1], 16;"
                    :: "r"(smem_u32(&as[row * PITCH + c16 * 4])),
                       "l"(A + (arow0 + row) * K + (long long)j * BK + c16 * 8)
                    : "memory");
            }
            #pragma unroll
            for (int i = 0; i < 4; i++) {               // B: 1024 16B chunks
                const int ch = tid + 256 * i;
                const int row = ch >> 2, c16 = ch & 3;
                asm volatile("cp.async.cg.shared.global [%0], [%1], 16;"
                    :: "r"(smem_u32(&bs[row * PITCH + c16 * 4])),
                       "l"(B + (bcol0 + row) * K + (long long)j * BK + c16 * 8)
                    : "memory");
            }
        }
        asm volatile("cp.async.commit_group;" ::: "memory");
    };

    float acc[4][8][4];
    #pragma unroll
    for (int i = 0; i < 4; i++)
        #pragma unroll
        for (int jn = 0; jn < 8; jn++)
            #pragma unroll
            for (int r = 0; r < 4; r++) acc[i][jn][r] = 0.f;

    issue(0); issue(1);

    for (int j = 0; j < nch; j++) {
        if (j == nch - 1) asm volatile("cp.async.wait_group 0;" ::: "memory");
        else              asm volatile("cp.async.wait_group 1;" ::: "memory");
        __syncthreads();
        issue(j + 2);

        const uint32_t* a_ = As + (j % 3) * ASTG;
        const uint32_t* b_ = Bs + (j % 3) * BSTG;

        #pragma unroll
        for (int ks = 0; ks < 2; ks++) {                // 2 x K=16 per chunk
            uint32_t af[4][4], bf[8][2];
            #pragma unroll
            for (int mt = 0; mt < 4; mt++) {
                const int r = wm * 64 + mt * 16 + g;
                const int c = ks * 8 + t;
                af[mt][0] = a_[r * PITCH + c];
                af[mt][1] = a_[(r + 8) * PITCH + c];
                af[mt][2] = a_[r * PITCH + c + 4];
                af[mt][3] = a_[(r + 8) * PITCH + c + 4];
            }
            #pragma unroll
            for (int nt = 0; nt < 8; nt++) {
                const int n = wn * 64 + nt * 8 + g;
                bf[nt][0] = b_[n * PITCH + ks * 8 + t];
                bf[nt][1] = b_[n * PITCH + ks * 8 + t + 4];
            }
            #pragma unroll
            for (int mt = 0; mt < 4; mt++)
                #pragma unroll
                for (int nt = 0; nt < 8; nt++)
                    asm volatile(
                        "mma.sync.aligned.m16n8k16.row.col.f32.f16.f16.f32 "
                        "{%0,%1,%2,%3}, {%4,%5,%6,%7}, {%8,%9}, {%0,%1,%2,%3};"
                        : "+f"(acc[mt][nt][0]), "+f"(acc[mt][nt][1]),
                          "+f"(acc[mt][nt][2]), "+f"(acc[mt][nt][3])
                        : "r"(af[mt][0]), "r"(af[mt][1]), "r"(af[mt][2]), "r"(af[mt][3]),
                          "r"(bf[nt][0]), "r"(bf[nt][1]));
        }
    }

    #pragma unroll
    for (int mt = 0; mt < 4; mt++) {
        const long long gr = arow0 + wm * 64 + mt * 16 + g;
        #pragma unroll
        for (int nt = 0; nt < 8; nt++) {
            const long long gc = bcol0 + wn * 64 + nt * 8 + 2 * t;
            float2 v0 = make_float2(acc[mt][nt][0] * alpha, acc[mt][nt][1] * alpha);
            float2 v1 = make_float2(acc[mt][nt][2] * alpha, acc[mt][nt][3] * alpha);
            *reinterpret_cast<float2*>(&C[gr * ldc + gc])       = v0;
            *reinterpret_cast<float2*>(&C[(gr + 8) * ldc + gc]) = v1;
        }
    }
}

// ---------------------------------------------------------------------------
// V transpose (fp16): [N, C] -> [C, N] per batch
// ---------------------------------------------------------------------------
__global__ __launch_bounds__(256) void vtrans_kernel(
    const __half* __restrict__ V, __half* __restrict__ Vt)
{
    __shared__ __half tb[32][33];
    const long long base = (long long)blockIdx.z * NN * CC;
    const int r0 = blockIdx.y * 32, c0 = blockIdx.x * 32;
    const int tx = threadIdx.x & 31, ty = threadIdx.x >> 5;
    #pragma unroll
    for (int i = ty; i < 32; i += 8)
        tb[i][tx] = V[base + (long long)(r0 + i) * CC + c0 + tx];
    __syncthreads();
    #pragma unroll
    for (int i = ty; i < 32; i += 8)
        Vt[base + (long long)(c0 + i) * NN + r0 + tx] = tb[tx][i];
}

// ---------------------------------------------------------------------------
// softmax over batch dim (axis=0): exact fp32 S -> out, fp16 S -> Sh
// ---------------------------------------------------------------------------
__global__ __launch_bounds__(256) void batch_softmax_kernel(
    const float* __restrict__ scores, float* __restrict__ S,
    __half* __restrict__ Sh)
{
    size_t idx = ((size_t)blockIdx.x * blockDim.x + threadIdx.x) * 4;
    float4 v[BB];
    float4 mx = make_float4(-1e30f, -1e30f, -1e30f, -1e30f);
    #pragma unroll
    for (int b = 0; b < BB; b++) {
        v[b] = *reinterpret_cast<const float4*>(&scores[(size_t)b * NN * NN + idx]);
        mx.x = fmaxf(mx.x, v[b].x); mx.y = fmaxf(mx.y, v[b].y);
        mx.z = fmaxf(mx.z, v[b].z); mx.w = fmaxf(mx.w, v[b].w);
    }
    float4 s = make_float4(0.f, 0.f, 0.f, 0.f);
    #pragma unroll
    for (int b = 0; b < BB; b++) {
        v[b].x = __expf(v[b].x - mx.x); s.x += v[b].x;
        v[b].y = __expf(v[b].y - mx.y); s.y += v[b].y;
        v[b].z = __expf(v[b].z - mx.z); s.z += v[b].z;
        v[b].w = __expf(v[b].w - mx.w); s.w += v[b].w;
    }
    const float4 inv = make_float4(1.f / s.x, 1.f / s.y, 1.f / s.z, 1.f / s.w);
    #pragma unroll
    for (int b = 0; b < BB; b++) {
        float4 o = make_float4(v[b].x * inv.x, v[b].y * inv.y,
                               v[b].z * inv.z, v[b].w * inv.w);
        *reinterpret_cast<float4*>(&S[(size_t)b * NN * NN + idx]) = o;
        *reinterpret_cast<__half2*>(&Sh[(size_t)b * NN * NN + idx])     =
            __floats2half2_rn(o.x, o.y);
        *reinterpret_cast<__half2*>(&Sh[(size_t)b * NN * NN + idx + 2]) =
            __floats2half2_rn(o.z, o.w);
    }
}

// ---------------------------------------------------------------------------
// P kernel (fp32 exact): P[row,m] = (|n-m| + sig*eps)/rowsum
// ---------------------------------------------------------------------------
__global__ __launch_bounds__(256) void p_kernel(
    const float* __restrict__ x, const float* __restrict__ Wsig,
    const float* __restrict__ eps, float* __restrict__ P)
{
    const int row = blockIdx.x;
    const int n = row & (NN - 1);
    const int tid = threadIdx.x;
    __shared__ float red[8];

    float part = x[(size_t)row * CC + tid] * Wsig[tid];
    #pragma unroll
    for (int o = 16; o > 0; o >>= 1) part += __shfl_xor_sync(0xffffffffu, part, o);
    if ((tid & 31) == 0) red[tid >> 5] = part;
    __syncthreads();
    float sig = red[0] + red[1] + red[2] + red[3] + red[4] + red[5] + red[6] + red[7];
    sig = fabsf(sig);
    __syncthreads();

    float4 e = *reinterpret_cast<const float4*>(&eps[(size_t)row * NN + tid * 4]);
    float ps = e.x + e.y + e.z + e.w;
    #pragma unroll
    for (int o = 16; o > 0; o >>= 1) ps += __shfl_xor_sync(0xffffffffu, ps, o);
    if ((tid & 31) == 0) red[tid >> 5] = ps;
    __syncthreads();
    float sum_eps = red[0] + red[1] + red[2] + red[3] + red[4] + red[5] + red[6] + red[7];

    float An = 0.5f * ((float)n * (float)(n + 1) +
                       (float)(NN - 1 - n) * (float)(NN - n));
    float inv = 1.0f / (An + sig * sum_eps);

    int m0 = tid * 4;
    float4 o4;
    o4.x = (fabsf((float)(n - (m0 + 0))) + sig * e.x) * inv;
    o4.y = (fabsf((float)(n - (m0 + 1))) + sig * e.y) * inv;
    o4.z = (fabsf((float)(n - (m0 + 2))) + sig * e.z) * inv;
    o4.w = (fabsf((float)(n - (m0 + 3))) + sig * e.w) * inv;
    *reinterpret_cast<float4*>(&P[(size_t)row * NN + m0]) = o4;
}

// ---------------------------------------------------------------------------
extern "C" void kernel_launch(void* const* d_in, const int* in_sizes, int n_in,
                              void* d_out, int out_size)
{
    const float* x   = (const float*)d_in[0];
    const float* Wq  = (const float*)d_in[1];
    const float* Wk  = (const float*)d_in[2];
    const float* Wv  = (const float*)d_in[3];
    const float* Ws  = (const float*)d_in[4];
    const float* eps = (const float*)d_in[5];
    float* out = (float*)d_out;

    __half *QKVh, *Vth, *Sh;
    float *scores;
    cudaGetSymbolAddress((void**)&QKVh, g_QKVh);
    cudaGetSymbolAddress((void**)&Vth, g_Vth);
    cudaGetSymbolAddress((void**)&Sh, g_Sh);
    cudaGetSymbolAddress((void**)&scores, g_scores);

    static cudaStream_t s_p = nullptr, s_v = nullptr;
    static cudaEvent_t ev_fork = nullptr, ev_join = nullptr,
                       ev_qkv = nullptr, ev_vt = nullptr;
    if (s_p == nullptr) {
        cudaStreamCreateWithFlags(&s_p, cudaStreamNonBlocking);
        cudaStreamCreateWithFlags(&s_v, cudaStreamNonBlocking);
        cudaEventCreateWithFlags(&ev_fork, cudaEventDisableTiming);
        cudaEventCreateWithFlags(&ev_join, cudaEventDisableTiming);
        cudaEventCreateWithFlags(&ev_qkv, cudaEventDisableTiming);
        cudaEventCreateWithFlags(&ev_vt, cudaEventDisableTiming);
    }

    const int SMEM_QKV = (3 * 128 * 36 + 3 * 32 * 264) * sizeof(float);   // 156,672
    const int SMEM_F16 = 3 * (128 * 20 + 256 * 20) * sizeof(uint32_t);    // 92,160
    cudaFuncSetAttribute((void*)qkv_gemm,
                         cudaFuncAttributeMaxDynamicSharedMemorySize, SMEM_QKV);
    cudaFuncSetAttribute((void*)mma_gemm_f16,
                         cudaFuncAttributeMaxDynamicSharedMemorySize, SMEM_F16);

    const long long QKV_SZ = (long long)BB * NN * CC;

    // fork: P runs concurrently with the whole attention chain
    cudaEventRecord(ev_fork, 0);
    cudaStreamWaitEvent(s_p, ev_fork, 0);
    p_kernel<<<BB * NN, 256, 0, s_p>>>(x, Ws, eps, out + OFF_P);
    cudaEventRecord(ev_join, s_p);

    // 1) Q/K/V = tf32(x) @ tf32(W) -> fp16
    qkv_gemm<<<dim3(1, (BB * NN) / 128, 3), 256, SMEM_QKV>>>(
        x, Wq, Wk, Wv, QKVh, QKV_SZ);
    cudaEventRecord(ev_qkv, 0);

    // 1b) Vt = transpose(V) fp16, overlapped with scores GEMM
    cudaStreamWaitEvent(s_v, ev_qkv, 0);
    vtrans_kernel<<<dim3(CC / 32, NN / 32, BB), 256, 0, s_v>>>(
        QKVh + 2 * QKV_SZ, Vth);
    cudaEventRecord(ev_vt, s_v);

    // 2) scores_b = Q_b @ K_b^T / 16  (fp16 MMA, fp32 out)
    mma_gemm_f16<<<dim3(NN / 256, NN / 128, BB), 256, SMEM_F16>>>(
        QKVh, QKVh + QKV_SZ, scores, CC, NN, 1.0f / 16.0f,
        (long long)NN * CC, (long long)NN * CC, (long long)NN * NN);

    // 3) softmax over batch dim: exact S -> out, fp16 S -> Sh
    batch_softmax_kernel<<<(NN * NN) / 1024, 256>>>(scores, out + OFF_S, Sh);

    // 4) Z_b = S_b @ Vt_b^T  (fp16 MMA, fp32 out)
    cudaStreamWaitEvent(0, ev_vt, 0);
    mma_gemm_f16<<<dim3(CC / 256, NN / 128, BB), 256, SMEM_F16>>>(
        Sh, Vth, out + OFF_Z, NN, CC, 1.0f,
        (long long)NN * NN, (long long)NN * CC, (long long)NN * CC);

    // join P
    cudaStreamWaitEvent(0, ev_join, 0);
}

// round 11
// speedup vs baseline: 1.2808x; 1.0788x over previous
#include <cuda_runtime.h>
#include <cuda_fp16.h>
#include <cstdint>

// ---------------------------------------------------------------------------
// AnomalyAttention B=16, N=1024, C=256
// QKV: mma.sync tf32 (fp32 in, fp16 out). scores/Z: mma.sync fp16 m16n8k16,
// 128x128 CTA / 64x32 warp tiles, ldmatrix fragment loads, 2 CTAs/SM.
// Outputs: Z [B,N,C] | P [B,N,N] | S [B,N,N]
// ---------------------------------------------------------------------------

#define BB 16
#define NN 1024
#define CC 256

static const long long OFF_Z = 0;
static const long long OFF_P = (long long)BB * NN * CC;
static const long long OFF_S = OFF_P + (long long)BB * NN * NN;

__device__ __half g_QKVh[(size_t)3 * BB * NN * CC];   // Q|K|V fp16, K-major
__device__ __half g_Vth[(size_t)BB * NN * CC];        // V^T fp16 [C,N] per batch
__device__ __half g_Sh[(size_t)BB * NN * NN];         // fp16 S for Z GEMM
__device__ float  g_scores[(size_t)BB * NN * NN];     // raw scores fp32

// ---------------------------------------------------------------------------
__device__ __forceinline__ uint32_t smem_u32(const void* p) {
    uint32_t a;
    asm("{ .reg .u64 t; cvta.to.shared.u64 t, %1; cvt.u32.u64 %0, t; }"
        : "=r"(a) : "l"(p));
    return a;
}
__device__ __forceinline__ uint32_t tf32u(uint32_t x) {
    float y;
    asm("cvt.rna.tf32.f32 %0, %1;" : "=f"(y) : "f"(__uint_as_float(x)));
    return __float_as_uint(y);
}

// ---------------------------------------------------------------------------
// QKV GEMM (tf32): C_h = round_f16( round_tf32(x) @ round_tf32(W) )
// A = x [M,256] fp32 K-major (shared across z); B = W_z [256,256] fp32 N-major.
// CTA 128x256, 256 thr, 8 warps (2Mx4N), warp 64x64, BK=32, 3-stage ring.
// ---------------------------------------------------------------------------
__global__ __launch_bounds__(256, 1) void qkv_gemm(
    const float* __restrict__ A, const float* __restrict__ B0,
    const float* __restrict__ B1, const float* __restrict__ B2,
    __half* __restrict__ C, long long sC)
{
    constexpr int BM = 128, BN = 256, BK = 32, K = CC, PAD = 36, PADN = 264;
    constexpr int ASTG = BM * PAD;
    constexpr int BSTG = BK * PADN;
    extern __shared__ float sm[];
    float* As = sm;
    float* Bs = sm + 3 * ASTG;

    const int z = blockIdx.z;
    const float* B = (z == 0 ? B0 : (z == 1 ? B1 : B2));
    C += (long long)z * sC;

    const int tid = threadIdx.x, lane = tid & 31, wid = tid >> 5;
    const int wm = wid >> 2, wn = wid & 3;
    const int g = lane >> 2, t = lane & 3;
    const long long arow0 = (long long)blockIdx.y * BM;
    const int nch = K / BK;

    auto issue = [&](int j) {
        if (j < nch) {
            const int st = j % 3;
            float* as = As + st * ASTG;
            float* bs = Bs + st * BSTG;
            #pragma unroll
            for (int i = 0; i < 4; i++) {
                const int ch = tid + 256 * i;
                const int row = ch >> 3, c16 = ch & 7;
                asm volatile("cp.async.cg.shared.global [%0], [%1], 16;"
                    :: "r"(smem_u32(&as[row * PAD + c16 * 4])),
                       "l"(A + (arow0 + row) * K + (long long)j * BK + c16 * 4)
                    : "memory");
            }
            #pragma unroll
            for (int i = 0; i < 8; i++) {
                const int ch = tid + 256 * i;
                const int row = ch >> 6, c4 = (ch & 63) * 4;
                asm volatile("cp.async.cg.shared.global [%0], [%1], 16;"
                    :: "r"(smem_u32(&bs[row * PADN + c4])),
                       "l"(B + ((long long)j * BK + row) * BN + c4)
                    : "memory");
            }
        }
        asm volatile("cp.async.commit_group;" ::: "memory");
    };

    float acc[4][8][4];
    #pragma unroll
    for (int i = 0; i < 4; i++)
        #pragma unroll
        for (int jn = 0; jn < 8; jn++)
            #pragma unroll
            for (int r = 0; r < 4; r++) acc[i][jn][r] = 0.f;

    issue(0); issue(1);

    for (int j = 0; j < nch; j++) {
        if (j == nch - 1) asm volatile("cp.async.wait_group 0;" ::: "memory");
        else              asm volatile("cp.async.wait_group 1;" ::: "memory");
        __syncthreads();
        issue(j + 2);

        const float* a_ = As + (j % 3) * ASTG;
        const float* b_ = Bs + (j % 3) * BSTG;

        #pragma unroll
        for (int ks = 0; ks < 4; ks++) {
            uint32_t af[4][4], bf[8][2];
            #pragma unroll
            for (int mt = 0; mt < 4; mt++) {
                const int r = wm * 64 + mt * 16 + g;
                const int c = ks * 8 + t;
                af[mt][0] = tf32u(__float_as_uint(a_[r * PAD + c]));
                af[mt][1] = tf32u(__float_as_uint(a_[(r + 8) * PAD + c]));
                af[mt][2] = tf32u(__float_as_uint(a_[r * PAD + c + 4]));
                af[mt][3] = tf32u(__float_as_uint(a_[(r + 8) * PAD + c + 4]));
            }
            #pragma unroll
            for (int nt = 0; nt < 8; nt++) {
                const int n = wn * 64 + nt * 8 + g;
                bf[nt][0] = tf32u(__float_as_uint(b_[(ks * 8 + t) * PADN + n]));
                bf[nt][1] = tf32u(__float_as_uint(b_[(ks * 8 + t + 4) * PADN + n]));
            }
            #pragma unroll
            for (int mt = 0; mt < 4; mt++)
                #pragma unroll
                for (int nt = 0; nt < 8; nt++)
                    asm volatile(
                        "mma.sync.aligned.m16n8k8.row.col.f32.tf32.tf32.f32 "
                        "{%0,%1,%2,%3}, {%4,%5,%6,%7}, {%8,%9}, {%0,%1,%2,%3};"
                        : "+f"(acc[mt][nt][0]), "+f"(acc[mt][nt][1]),
                          "+f"(acc[mt][nt][2]), "+f"(acc[mt][nt][3])
                        : "r"(af[mt][0]), "r"(af[mt][1]), "r"(af[mt][2]), "r"(af[mt][3]),
                          "r"(bf[nt][0]), "r"(bf[nt][1]));
        }
    }

    #pragma unroll
    for (int mt = 0; mt < 4; mt++) {
        const long long gr = arow0 + wm * 64 + mt * 16 + g;
        #pragma unroll
        for (int nt = 0; nt < 8; nt++) {
            const long long gc = wn * 64 + nt * 8 + 2 * t;
            *reinterpret_cast<__half2*>(&C[gr * BN + gc]) =
                __floats2half2_rn(acc[mt][nt][0], acc[mt][nt][1]);
            *reinterpret_cast<__half2*>(&C[(gr + 8) * BN + gc]) =
                __floats2half2_rn(acc[mt][nt][2], acc[mt][nt][3]);
        }
    }
}

// ---------------------------------------------------------------------------
// fp16 GEMM: C(fp32) = alpha * A * B^T
// A [M,K] half K-major, B [N,K] half K-major. K%32==0.
// CTA 128x128, 256 thr, 8 warps (2Mx4N), warp 64x32, m16n8k16,
// BK=32 halves, 3-stage ring, ldmatrix.x4 fragment loads, 2 CTAs/SM.
// smem pitch 20 u32/row: ldmatrix phase banks {20r%32}+0..3 cover all 32.
// ---------------------------------------------------------------------------
__global__ __launch_bounds__(256, 2) void mma_gemm_f16(
    const __half* __restrict__ A, const __half* __restrict__ B,
    float* __restrict__ C,
    int K, int ldc, float alpha, long long sA, long long sB, long long sC)
{
    constexpr int BM = 128, BN = 128, BK = 32, PITCH = 20;
    constexpr int ASTG = BM * PITCH;    // 2560 u32
    constexpr int BSTG = BN * PITCH;    // 2560 u32
    extern __shared__ uint32_t smh[];
    uint32_t* As = smh;
    uint32_t* Bs = smh + 3 * ASTG;

    const int z = blockIdx.z;
    A += (long long)z * sA;
    B += (long long)z * sB;
    C += (long long)z * sC;

    const int tid = threadIdx.x, lane = tid & 31, wid = tid >> 5;
    const int wm = wid >> 2, wn = wid & 3;           // 2M x 4N warps
    const int g = lane >> 2, t = lane & 3;
    const long long arow0 = (long long)blockIdx.y * BM;
    const long long bcol0 = (long long)blockIdx.x * BN;
    const int nch = K / BK;

    // per-lane ldmatrix address components
    const int a_row = wm * 64 + (lane & 15);         // + mt*16
    const int a_col = (lane >> 4) * 4;               // + ks*8
    const int b_row = wn * 32 + ((lane >> 4) << 3) + (lane & 7);   // + nt2*16
    const int b_col = ((lane >> 3) & 1) * 4;         // + ks*8

    auto issue = [&](int j) {
        if (j < nch) {
            const int st = j % 3;
            uint32_t* as = As + st * ASTG;
            uint32_t* bs = Bs + st * BSTG;
            #pragma unroll
            for (int i = 0; i < 2; i++) {            // A: 512 16B chunks
                const int ch = tid + 256 * i;
                const int row = ch >> 2, c16 = ch & 3;
                asm volatile("cp.async.cg.shared.global [%0], [%1], 16;"
                    :: "r"(smem_u32(&as[row * PITCH + c16 * 4])),
                       "l"(A + (arow0 + row) * K + (long long)j * BK + c16 * 8)
                    : "memory");
            }
            #pragma unroll
            for (int i = 0; i < 2; i++) {            // B: 512 16B chunks
                const int ch = tid + 256 * i;
                const int row = ch >> 2, c16 = ch & 3;
                asm volatile("cp.async.cg.shared.global [%0], [%1], 16;"
                    :: "r"(smem_u32(&bs[row * PITCH + c16 * 4])),
                       "l"(B + (bcol0 + row) * K + (long long)j * BK + c16 * 8)
                    : "memory");
            }
        }
        asm volatile("cp.async.commit_group;" ::: "memory");
    };

    float acc[4][4][4];
    #pragma unroll
    for (int i = 0; i < 4; i++)
        #pragma unroll
        for (int jn = 0; jn < 4; jn++)
            #pragma unroll
            for (int r = 0; r < 4; r++) acc[i][jn][r] = 0.f;

    issue(0); issue(1);

    for (int j = 0; j < nch; j++) {
        if (j == nch - 1) asm volatile("cp.async.wait_group 0;" ::: "memory");
        else              asm volatile("cp.async.wait_group 1;" ::: "memory");
        __syncthreads();
        issue(j + 2);

        const uint32_t as0 = smem_u32(As + (j % 3) * ASTG);
        const uint32_t bs0 = smem_u32(Bs + (j % 3) * BSTG);

        #pragma unroll
        for (int ks = 0; ks < 2; ks++) {             // 2 x K=16 per chunk
            uint32_t af[4][4], bf[4][2];
            #pragma unroll
            for (int mt = 0; mt < 4; mt++) {
                const uint32_t addr = as0 +
                    (((a_row + mt * 16) * PITCH) + ks * 8 + a_col) * 4;
                asm volatile(
                    "ldmatrix.sync.aligned.m8n8.x4.shared.b16 {%0,%1,%2,%3}, [%4];"
                    : "=r"(af[mt][0]), "=r"(af[mt][1]),
                      "=r"(af[mt][2]), "=r"(af[mt][3])
                    : "r"(addr));
            }
            #pragma unroll
            for (int nt2 = 0; nt2 < 2; nt2++) {      // each covers 2 nt
                const uint32_t addr = bs0 +
                    (((b_row + nt2 * 16) * PITCH) + ks * 8 + b_col) * 4;
                asm volatile(
                    "ldmatrix.sync.aligned.m8n8.x4.shared.b16 {%0,%1,%2,%3}, [%4];"
                    : "=r"(bf[nt2 * 2][0]), "=r"(bf[nt2 * 2][1]),
                      "=r"(bf[nt2 * 2 + 1][0]), "=r"(bf[nt2 * 2 + 1][1])
                    : "r"(addr));
            }
            #pragma unroll
            for (int mt = 0; mt < 4; mt++)
                #pragma unroll
                for (int nt = 0; nt < 4; nt++)
                    asm volatile(
                        "mma.sync.aligned.m16n8k16.row.col.f32.f16.f16.f32 "
                        "{%0,%1,%2,%3}, {%4,%5,%6,%7}, {%8,%9}, {%0,%1,%2,%3};"
                        : "+f"(acc[mt][nt][0]), "+f"(acc[mt][nt][1]),
                          "+f"(acc[mt][nt][2]), "+f"(acc[mt][nt][3])
                        : "r"(af[mt][0]), "r"(af[mt][1]), "r"(af[mt][2]), "r"(af[mt][3]),
                          "r"(bf[nt][0]), "r"(bf[nt][1]));
        }
    }

    #pragma unroll
    for (int mt = 0; mt < 4; mt++) {
        const long long gr = arow0 + wm * 64 + mt * 16 + g;
        #pragma unroll
        for (int nt = 0; nt < 4; nt++) {
            const long long gc = bcol0 + wn * 32 + nt * 8 + 2 * t;
            float2 v0 = make_float2(acc[mt][nt][0] * alpha, acc[mt][nt][1] * alpha);
            float2 v1 = make_float2(acc[mt][nt][2] * alpha, acc[mt][nt][3] * alpha);
            *reinterpret_cast<float2*>(&C[gr * ldc + gc])       = v0;
            *reinterpret_cast<float2*>(&C[(gr + 8) * ldc + gc]) = v1;
        }
    }
}

// ---------------------------------------------------------------------------
// V transpose (fp16): [N, C] -> [C, N] per batch
// ---------------------------------------------------------------------------
__global__ __launch_bounds__(256) void vtrans_kernel(
    const __half* __restrict__ V, __half* __restrict__ Vt)
{
    __shared__ __half tb[32][33];
    const long long base = (long long)blockIdx.z * NN * CC;
    const int r0 = blockIdx.y * 32, c0 = blockIdx.x * 32;
    const int tx = threadIdx.x & 31, ty = threadIdx.x >> 5;
    #pragma unroll
    for (int i = ty; i < 32; i += 8)
        tb[i][tx] = V[base + (long long)(r0 + i) * CC + c0 + tx];
    __syncthreads();
    #pragma unroll
    for (int i = ty; i < 32; i += 8)
        Vt[base + (long long)(c0 + i) * NN + r0 + tx] = tb[tx][i];
}

// ---------------------------------------------------------------------------
// softmax over batch dim (axis=0): exact fp32 S -> out, fp16 S -> Sh
// ---------------------------------------------------------------------------
__global__ __launch_bounds__(256) void batch_softmax_kernel(
    const float* __restrict__ scores, float* __restrict__ S,
    __half* __restrict__ Sh)
{
    size_t idx = ((size_t)blockIdx.x * blockDim.x + threadIdx.x) * 4;
    float4 v[BB];
    float4 mx = make_float4(-1e30f, -1e30f, -1e30f, -1e30f);
    #pragma unroll
    for (int b = 0; b < BB; b++) {
        v[b] = *reinterpret_cast<const float4*>(&scores[(size_t)b * NN * NN + idx]);
        mx.x = fmaxf(mx.x, v[b].x); mx.y = fmaxf(mx.y, v[b].y);
        mx.z = fmaxf(mx.z, v[b].z); mx.w = fmaxf(mx.w, v[b].w);
    }
    float4 s = make_float4(0.f, 0.f, 0.f, 0.f);
    #pragma unroll
    for (int b = 0; b < BB; b++) {
        v[b].x = __expf(v[b].x - mx.x); s.x += v[b].x;
        v[b].y = __expf(v[b].y - mx.y); s.y += v[b].y;
        v[b].z = __expf(v[b].z - mx.z); s.z += v[b].z;
        v[b].w = __expf(v[b].w - mx.w); s.w += v[b].w;
    }
    const float4 inv = make_float4(1.f / s.x, 1.f / s.y, 1.f / s.z, 1.f / s.w);
    #pragma unroll
    for (int b = 0; b < BB; b++) {
        float4 o = make_float4(v[b].x * inv.x, v[b].y * inv.y,
                               v[b].z * inv.z, v[b].w * inv.w);
        *reinterpret_cast<float4*>(&S[(size_t)b * NN * NN + idx]) = o;
        *reinterpret_cast<__half2*>(&Sh[(size_t)b * NN * NN + idx])     =
            __floats2half2_rn(o.x, o.y);
        *reinterpret_cast<__half2*>(&Sh[(size_t)b * NN * NN + idx + 2]) =
            __floats2half2_rn(o.z, o.w);
    }
}

// ---------------------------------------------------------------------------
// P kernel (fp32 exact): P[row,m] = (|n-m| + sig*eps)/rowsum
// ---------------------------------------------------------------------------
__global__ __launch_bounds__(256) void p_kernel(
    const float* __restrict__ x, const float* __restrict__ Wsig,
    const float* __restrict__ eps, float* __restrict__ P)
{
    const int row = blockIdx.x;
    const int n = row & (NN - 1);
    const int tid = threadIdx.x;
    __shared__ float red[8];

    float part = x[(size_t)row * CC + tid] * Wsig[tid];
    #pragma unroll
    for (int o = 16; o > 0; o >>= 1) part += __shfl_xor_sync(0xffffffffu, part, o);
    if ((tid & 31) == 0) red[tid >> 5] = part;
    __syncthreads();
    float sig = red[0] + red[1] + red[2] + red[3] + red[4] + red[5] + red[6] + red[7];
    sig = fabsf(sig);
    __syncthreads();

    float4 e = *reinterpret_cast<const float4*>(&eps[(size_t)row * NN + tid * 4]);
    float ps = e.x + e.y + e.z + e.w;
    #pragma unroll
    for (int o = 16; o > 0; o >>= 1) ps += __shfl_xor_sync(0xffffffffu, ps, o);
    if ((tid & 31) == 0) red[tid >> 5] = ps;
    __syncthreads();
    float sum_eps = red[0] + red[1] + red[2] + red[3] + red[4] + red[5] + red[6] + red[7];

    float An = 0.5f * ((float)n * (float)(n + 1) +
                       (float)(NN - 1 - n) * (float)(NN - n));
    float inv = 1.0f / (An + sig * sum_eps);

    int m0 = tid * 4;
    float4 o4;
    o4.x = (fabsf((float)(n - (m0 + 0))) + sig * e.x) * inv;
    o4.y = (fabsf((float)(n - (m0 + 1))) + sig * e.y) * inv;
    o4.z = (fabsf((float)(n - (m0 + 2))) + sig * e.z) * inv;
    o4.w = (fabsf((float)(n - (m0 + 3))) + sig * e.w) * inv;
    *reinterpret_cast<float4*>(&P[(size_t)row * NN + m0]) = o4;
}

// ---------------------------------------------------------------------------
extern "C" void kernel_launch(void* const* d_in, const int* in_sizes, int n_in,
                              void* d_out, int out_size)
{
    const float* x   = (const float*)d_in[0];
    const float* Wq  = (const float*)d_in[1];
    const float* Wk  = (const float*)d_in[2];
    const float* Wv  = (const float*)d_in[3];
    const float* Ws  = (const float*)d_in[4];
    const float* eps = (const float*)d_in[5];
    float* out = (float*)d_out;

    __half *QKVh, *Vth, *Sh;
    float *scores;
    cudaGetSymbolAddress((void**)&QKVh, g_QKVh);
    cudaGetSymbolAddress((void**)&Vth, g_Vth);
    cudaGetSymbolAddress((void**)&Sh, g_Sh);
    cudaGetSymbolAddress((void**)&scores, g_scores);

    static cudaStream_t s_p = nullptr, s_v = nullptr;
    static cudaEvent_t ev_fork = nullptr, ev_join = nullptr,
                       ev_qkv = nullptr, ev_vt = nullptr;
    if (s_p == nullptr) {
        cudaStreamCreateWithFlags(&s_p, cudaStreamNonBlocking);
        cudaStreamCreateWithFlags(&s_v, cudaStreamNonBlocking);
        cudaEventCreateWithFlags(&ev_fork, cudaEventDisableTiming);
        cudaEventCreateWithFlags(&ev_join, cudaEventDisableTiming);
        cudaEventCreateWithFlags(&ev_qkv, cudaEventDisableTiming);
        cudaEventCreateWithFlags(&ev_vt, cudaEventDisableTiming);
    }

    const int SMEM_QKV = (3 * 128 * 36 + 3 * 32 * 264) * sizeof(float);   // 156,672
    const int SMEM_F16 = 3 * (128 * 20 + 128 * 20) * sizeof(uint32_t);    // 61,440
    cudaFuncSetAttribute((void*)qkv_gemm,
                         cudaFuncAttributeMaxDynamicSharedMemorySize, SMEM_QKV);
    cudaFuncSetAttribute((void*)mma_gemm_f16,
                         cudaFuncAttributeMaxDynamicSharedMemorySize, SMEM_F16);

    const long long QKV_SZ = (long long)BB * NN * CC;

    // fork: P runs concurrently with the whole attention chain
    cudaEventRecord(ev_fork, 0);
    cudaStreamWaitEvent(s_p, ev_fork, 0);
    p_kernel<<<BB * NN, 256, 0, s_p>>>(x, Ws, eps, out + OFF_P);
    cudaEventRecord(ev_join, s_p);

    // 1) Q/K/V = tf32(x) @ tf32(W) -> fp16
    qkv_gemm<<<dim3(1, (BB * NN) / 128, 3), 256, SMEM_QKV>>>(
        x, Wq, Wk, Wv, QKVh, QKV_SZ);
    cudaEventRecord(ev_qkv, 0);

    // 1b) Vt = transpose(V) fp16, overlapped with scores GEMM
    cudaStreamWaitEvent(s_v, ev_qkv, 0);
    vtrans_kernel<<<dim3(CC / 32, NN / 32, BB), 256, 0, s_v>>>(
        QKVh + 2 * QKV_SZ, Vth);
    cudaEventRecord(ev_vt, s_v);

    // 2) scores_b = Q_b @ K_b^T / 16  (fp16 MMA, fp32 out)
    mma_gemm_f16<<<dim3(NN / 128, NN / 128, BB), 256, SMEM_F16>>>(
        QKVh, QKVh + QKV_SZ, scores, CC, NN, 1.0f / 16.0f,
        (long long)NN * CC, (long long)NN * CC, (long long)NN * NN);

    // 3) softmax over batch dim: exact S -> out, fp16 S -> Sh
    batch_softmax_kernel<<<(NN * NN) / 1024, 256>>>(scores, out + OFF_S, Sh);

    // 4) Z_b = S_b @ Vt_b^T  (fp16 MMA, fp32 out)
    cudaStreamWaitEvent(0, ev_vt, 0);
    mma_gemm_f16<<<dim3(CC / 128, NN / 128, BB), 256, SMEM_F16>>>(
        Sh, Vth, out + OFF_Z, NN, CC, 1.0f,
        (long long)NN * NN, (long long)NN * CC, (long long)NN * CC);

    // join P
    cudaStreamWaitEvent(0, ev_join, 0);
}